// round 3
// baseline (speedup 1.0000x reference)
#include <cuda_runtime.h>
#include <math.h>

#define BATCH 128
#define SEQ   512
#define EMB   512
#define HID   512
#define G4    2048
#define NQ    8
#define TAGS  50
#define NB2   128   // persistent recurrence blocks (<= SM count, co-resident)

typedef unsigned long long ull;

// packed dual-fp32 FMA: d.lo += a.lo*b.lo ; d.hi += a.hi*b.hi
#define FMA2(acc, a, b) \
    asm("fma.rn.f32x2 %0, %1, %2, %0;" : "+l"(acc) : "l"(a), "l"(b))

__device__ __forceinline__ ull dupf(float v) {
    ull r;
    asm("mov.b64 %0, {%1, %1};" : "=l"(r) : "r"(__float_as_uint(v)));
    return r;
}
__device__ __forceinline__ float f2lo(ull v) { return __uint_as_float((unsigned)(v)); }
__device__ __forceinline__ float f2hi(ull v) { return __uint_as_float((unsigned)(v >> 32)); }

// ---------------- device scratch ----------------
__device__ float    g_Z[(size_t)SEQ * G4 * BATCH];  // [t][j][b]
__device__ float    g_h[2][HID][BATCH];             // double-buffered hidden [k][b]
__device__ unsigned g_bar;

// fast activations
__device__ __forceinline__ float sigf(float v)  { return 1.f / (1.f + __expf(-v)); }
__device__ __forceinline__ float tanhfast(float v) { return 1.f - 2.f / (__expf(2.f * v) + 1.f); }

// ---------------- kernel 1: Zx = x @ Wih^T + (bih + bhh) ----------------
// grid (16, 512): by = t, bx = 128-wide j tile. 256 thr.
// FMA2 pairing along j: weight pairs natural (float2 from smem), h duplicated in smem.
__global__ void __launch_bounds__(256, 2) gates_gemm(const float* __restrict__ x,
                                                     const float* __restrict__ Wih,
                                                     const float* __restrict__ bih,
                                                     const float* __restrict__ bhh)
{
    const int t  = blockIdx.y;
    const int j0 = blockIdx.x * 128;
    __shared__ __align__(16) ull   xs_dup[32][128];  // (h,h) duplicated, 32 KB
    __shared__ __align__(16) float ws[32][128];      // Wih chunk [e][j], 16 KB
    const int tid = threadIdx.x;
    const int tx = tid & 15;   // 4 j-pairs: jp = tx + 16*u
    const int ty = tid >> 4;   // batches ty*8 .. ty*8+7

    ull acc2[4][8];
#pragma unroll
    for (int a = 0; a < 4; a++)
#pragma unroll
        for (int b = 0; b < 8; b++) acc2[a][b] = 0ull;

    for (int e0 = 0; e0 < EMB; e0 += 32) {
#pragma unroll
        for (int i = 0; i < 4; i++) {            // x chunk -> xs_dup[e][b] (duplicated)
            int lid = tid + i * 256;             // 0..1023
            int b   = lid & 127;
            int ev  = lid >> 7;                  // 0..7
            float4 v = *(const float4*)&x[(size_t)b * (SEQ * EMB) + (size_t)t * EMB + e0 + ev * 4];
            xs_dup[ev * 4 + 0][b] = dupf(v.x);
            xs_dup[ev * 4 + 1][b] = dupf(v.y);
            xs_dup[ev * 4 + 2][b] = dupf(v.z);
            xs_dup[ev * 4 + 3][b] = dupf(v.w);
        }
#pragma unroll
        for (int i = 0; i < 4; i++) {            // Wih chunk -> ws[e][j]
            int lid = tid + i * 256;
            int jj  = lid & 127;
            int ev  = lid >> 7;
            float4 v = *(const float4*)&Wih[(size_t)(j0 + jj) * EMB + e0 + ev * 4];
            ws[ev * 4 + 0][jj] = v.x;
            ws[ev * 4 + 1][jj] = v.y;
            ws[ev * 4 + 2][jj] = v.z;
            ws[ev * 4 + 3][jj] = v.w;
        }
        __syncthreads();
#pragma unroll 4
        for (int e = 0; e < 32; e++) {
            ull w2[4];
#pragma unroll
            for (int u = 0; u < 4; u++)          // natural float2 pair (w_j, w_j+1); strided => conflict-free
                w2[u] = *(const ull*)&ws[e][2 * (tx + 16 * u)];
            ull hd[8];
            const ulonglong2* xrow = (const ulonglong2*)&xs_dup[e][ty * 8];
#pragma unroll
            for (int q = 0; q < 4; q++) {        // broadcast loads
                ulonglong2 p = xrow[q];
                hd[2 * q + 0] = p.x;
                hd[2 * q + 1] = p.y;
            }
#pragma unroll
            for (int u = 0; u < 4; u++)
#pragma unroll
                for (int b = 0; b < 8; b++)
                    FMA2(acc2[u][b], w2[u], hd[b]);
        }
        __syncthreads();
    }
    // epilogue: unpack pairs, add bias, store
#pragma unroll
    for (int u = 0; u < 4; u++) {
        int jp = tx + 16 * u;
        int je = j0 + 2 * jp;                    // even col
        float be = bih[je] + bhh[je];
        float bo = bih[je + 1] + bhh[je + 1];
        float* de = &g_Z[((size_t)t * G4 + je) * BATCH + ty * 8];
        float* dod = &g_Z[((size_t)t * G4 + je + 1) * BATCH + ty * 8];
#pragma unroll
        for (int h = 0; h < 2; h++) {
            float4 ve, vo;
            ve.x = f2lo(acc2[u][h * 4 + 0]) + be; vo.x = f2hi(acc2[u][h * 4 + 0]) + bo;
            ve.y = f2lo(acc2[u][h * 4 + 1]) + be; vo.y = f2hi(acc2[u][h * 4 + 1]) + bo;
            ve.z = f2lo(acc2[u][h * 4 + 2]) + be; vo.z = f2hi(acc2[u][h * 4 + 2]) + bo;
            ve.w = f2lo(acc2[u][h * 4 + 3]) + be; vo.w = f2hi(acc2[u][h * 4 + 3]) + bo;
            *(float4*)&de[h * 4]  = ve;
            *(float4*)&dod[h * 4] = vo;
        }
    }
}

// ---------------- barrier helpers ----------------
__global__ void __launch_bounds__(32) bar_init() { if (threadIdx.x == 0) g_bar = 0u; }

__device__ __forceinline__ void grid_bar(unsigned target)
{
    __syncthreads();
    if (threadIdx.x == 0) {
        __threadfence();
        atomicAdd(&g_bar, 1u);
        unsigned v;
        do {
            asm volatile("ld.global.cg.u32 %0, [%1];" : "=r"(v) : "l"(&g_bar));
        } while (v < target);
    }
    __syncthreads();
}

// ---------------- kernel 2: persistent LSTM recurrence ----------------
// 128 blocks x 256 threads. Block bk owns hidden units k0..k0+3 x 4 gates (16 cols).
// FMA2 pairing along batch: h pairs natural from v2.u64 L2 load, w duplicated (2 movs/k).
__global__ void __launch_bounds__(256) lstm_rec(const float* __restrict__ Whh)
{
    const int bk  = blockIdx.x;
    const int k0  = bk * 4;
    const int tid = threadIdx.x;
    __shared__ __align__(16) float ws[HID][16];   // [k][cj]  32 KB
    __shared__ float zbuf[16][BATCH];             // 8 KB
    __shared__ float cs[4][BATCH];                // 2 KB

    for (int idx = tid; idx < HID * 16; idx += 256) {
        int k = idx >> 4, cj = idx & 15;
        int gate = cj >> 2, jj = cj & 3;
        ws[k][cj] = Whh[(size_t)(gate * HID + k0 + jj) * HID + k];
    }
    for (int e = tid; e < 4 * BATCH; e += 256) {
        int jj = e >> 7, b = e & 127;
        cs[jj][b] = 0.f;
        g_h[0][k0 + jj][b] = 0.f;
    }
    grid_bar(1 * NB2);

    const int tx = tid & 7;       // cols cj = tx*2, tx*2+1
    const int ty = tid >> 3;      // batches b0 = ty*4 .. +3
    const int b0 = ty * 4;
    int p = 0;

    for (int t = 0; t < SEQ; t++) {
        // prefetch this step's input-gate pre-activations (DRAM) early
        const int cj0 = tx * 2, cj1 = cj0 + 1;
        const int jg0 = (cj0 >> 2) * HID + k0 + (cj0 & 3);
        const int jg1 = (cj1 >> 2) * HID + k0 + (cj1 & 3);
        float4 z0 = *(const float4*)&g_Z[((size_t)t * G4 + jg0) * BATCH + b0];
        float4 z1 = *(const float4*)&g_Z[((size_t)t * G4 + jg1) * BATCH + b0];

        ull a00 = 0, a01 = 0, a10 = 0, a11 = 0;   // [col][batch-pair]
        const float* hb = &g_h[p][0][0];
#pragma unroll 8
        for (int k = 0; k < HID; k++) {
            ull h01, h23;
            asm volatile("ld.global.cg.v2.u64 {%0,%1}, [%2];"
                         : "=l"(h01), "=l"(h23)
                         : "l"(hb + (size_t)k * BATCH + b0));
            float2 wv = *(const float2*)&ws[k][tx * 2];
            ull w0 = dupf(wv.x);
            ull w1 = dupf(wv.y);
            FMA2(a00, w0, h01); FMA2(a01, w0, h23);
            FMA2(a10, w1, h01); FMA2(a11, w1, h23);
        }
        zbuf[cj0][b0 + 0] = f2lo(a00) + z0.x;
        zbuf[cj0][b0 + 1] = f2hi(a00) + z0.y;
        zbuf[cj0][b0 + 2] = f2lo(a01) + z0.z;
        zbuf[cj0][b0 + 3] = f2hi(a01) + z0.w;
        zbuf[cj1][b0 + 0] = f2lo(a10) + z1.x;
        zbuf[cj1][b0 + 1] = f2hi(a10) + z1.y;
        zbuf[cj1][b0 + 2] = f2lo(a11) + z1.z;
        zbuf[cj1][b0 + 3] = f2hi(a11) + z1.w;
        __syncthreads();
        for (int e = tid; e < 4 * BATCH; e += 256) {
            int jj = e >> 7, b = e & 127;
            float zi = zbuf[0 * 4 + jj][b];
            float zf = zbuf[1 * 4 + jj][b];
            float zg = zbuf[2 * 4 + jj][b];
            float zo = zbuf[3 * 4 + jj][b];
            float c  = sigf(zf) * cs[jj][b] + sigf(zi) * tanhfast(zg);
            cs[jj][b] = c;
            __stcg(&g_h[p ^ 1][k0 + jj][b], sigf(zo) * tanhfast(c));
        }
        p ^= 1;
        grid_bar(((unsigned)t + 2) * NB2);
    }
}

// ---------------- kernel 3: quantum gates + logits + log_softmax ----------------
__global__ void __launch_bounds__(256) tail_kernel(const float* __restrict__ Wf, const float* __restrict__ bf,
                                                   const float* __restrict__ Wu, const float* __restrict__ bu,
                                                   const float* __restrict__ Wo, const float* __restrict__ bo,
                                                   const float* __restrict__ thf, const float* __restrict__ thu,
                                                   const float* __restrict__ tho,
                                                   const float* __restrict__ Wt, const float* __restrict__ bt,
                                                   float* __restrict__ out)
{
    const int b = blockIdx.x;
    const int warp = threadIdx.x >> 5, lane = threadIdx.x & 31;
    __shared__ float v[3][NQ];
    __shared__ float ho[NQ];
    __shared__ float lg[TAGS];
    __shared__ float red[2];

    for (int r = 0; r < 3; r++) {
        const float* W = (r == 0) ? Wf : ((r == 1) ? Wu : Wo);
        float s = 0.f;
        for (int k = lane; k < HID; k += 32)
            s += g_h[0][k][b] * W[warp * HID + k];
#pragma unroll
        for (int o = 16; o; o >>= 1) s += __shfl_xor_sync(0xFFFFFFFFu, s, o);
        if (lane == 0) v[r][warp] = s;
    }
    __syncthreads();
    if (threadIdx.x < NQ) {
        int q = threadIdx.x;
        float fv = sigf(cosf(v[0][q] + bf[q] + thf[q]));
        float gv = tanhf(cosf(v[1][q] + bu[q] + thu[q]));
        float ov = sigf(cosf(v[2][q] + bo[q] + tho[q]));
        ho[q] = ov * tanhf(fv * gv);
    }
    __syncthreads();
    if (threadIdx.x < TAGS) {
        float s = bt[threadIdx.x];
#pragma unroll
        for (int q = 0; q < NQ; q++) s += ho[q] * Wt[threadIdx.x * NQ + q];
        lg[threadIdx.x] = s;
    }
    __syncthreads();
    if (threadIdx.x == 0) {
        float m = -1e30f;
        for (int i = 0; i < TAGS; i++) m = fmaxf(m, lg[i]);
        float se = 0.f;
        for (int i = 0; i < TAGS; i++) se += expf(lg[i] - m);
        red[0] = m; red[1] = logf(se);
    }
    __syncthreads();
    if (threadIdx.x < TAGS)
        out[(size_t)b * TAGS + threadIdx.x] = lg[threadIdx.x] - red[0] - red[1];
}

// ---------------- launch ----------------
extern "C" void kernel_launch(void* const* d_in, const int* in_sizes, int n_in,
                              void* d_out, int out_size)
{
    const float* x   = (const float*)d_in[0];
    const float* Wih = (const float*)d_in[1];
    const float* Whh = (const float*)d_in[2];
    const float* bih = (const float*)d_in[3];
    const float* bhh = (const float*)d_in[4];
    const float* Wf  = (const float*)d_in[5];
    const float* bf  = (const float*)d_in[6];
    const float* Wu  = (const float*)d_in[9];
    const float* bu  = (const float*)d_in[10];
    const float* Wo  = (const float*)d_in[11];
    const float* bo  = (const float*)d_in[12];
    const float* thf = (const float*)d_in[13];
    const float* thu = (const float*)d_in[15];
    const float* tho = (const float*)d_in[16];
    const float* Wt  = (const float*)d_in[17];
    const float* bt  = (const float*)d_in[18];
    float* out = (float*)d_out;

    dim3 g1(16, 512);
    gates_gemm<<<g1, 256>>>(x, Wih, bih, bhh);
    bar_init<<<1, 32>>>();
    lstm_rec<<<NB2, 256>>>(Whh);
    tail_kernel<<<BATCH, 256>>>(Wf, bf, Wu, bu, Wo, bo, thf, thu, tho, Wt, bt, out);
}